// round 16
// baseline (speedup 1.0000x reference)
#include <cuda_runtime.h>
#include <cuda_fp16.h>
#include <cstdint>
#include <math.h>

#define T_SEQ   4096
#define DM      1024
#define DFF     4096
#define NHEADS  16
#define HDIM    64
#define LN_EPS  1e-5f

// ---- arch-specific feature gate: tcgen05 only exists on sm_10xa/f targets ----
#if defined(__CUDA_ARCH__)
#  if defined(__CUDA_ARCH_FEAT_SM103_ALL) || defined(__CUDA_ARCH_FEAT_SM100_ALL) || defined(__CUDA_ARCH_FEAT_SM101_ALL)
#    define GEMM_TC 1
#  elif defined(__CUDA_ARCH_SPECIFIC__)
#    define GEMM_TC ((__CUDA_ARCH_SPECIFIC__ >= 1000) ? 1 : 0)
#  elif defined(__CUDA_ARCH_FAMILY_SPECIFIC__)
#    define GEMM_TC ((__CUDA_ARCH_FAMILY_SPECIFIC__ >= 1000) ? 1 : 0)
#  else
#    define GEMM_TC 0
#  endif
#else
#  define GEMM_TC 0
#endif

// ---------------- scratch (static device globals; no allocation) ----------------
static __device__ float g_x2 [T_SEQ * DM];           // residual after attn (fp32)
// fp16 weights [N,K] K-major
static __device__ __half g_wqkv16[3 * DM * DM];
static __device__ __half g_wo16  [DM * DM];
static __device__ __half g_w1_16 [DFF * DM];
static __device__ __half g_w2_16 [DM * DFF];
// fp16 activations
static __device__ __half g_ln16[T_SEQ * DM];   // LN1 out, then LN2 out (sequential reuse)
static __device__ __half g_y16 [T_SEQ * DM];   // attention out
static __device__ __half g_ff16[T_SEQ * DFF];  // gelu out
// fp16 attention operands written by the QKV GEMM epilogue, all [h][t][d]
static __device__ __half g_q16[NHEADS * T_SEQ * HDIM];   // scaled log2e/8
static __device__ __half g_k16[NHEADS * T_SEQ * HDIM];
static __device__ __half g_v16[NHEADS * T_SEQ * HDIM];

#define QSCALE 0.18033688011112042f   // (1/8) * log2(e)

// ---------------- helpers ----------------
__device__ __forceinline__ uint32_t packh(float hi, float lo) {
    uint32_t r;
    asm("cvt.rn.f16x2.f32 %0, %1, %2;" : "=r"(r) : "f"(hi), "f"(lo));
    return r;
}

__device__ __forceinline__ float ex2(float x) {
    float r;
    asm("ex2.approx.f32 %0, %1;" : "=f"(r) : "f"(x));
    return r;
}

__device__ __forceinline__ uint32_t ex2h2(uint32_t x) {
    uint32_t r;
    asm("ex2.approx.f16x2 %0, %1;" : "=r"(r) : "r"(x));
    return r;
}

__device__ __forceinline__ void mma_f16(float* c,
    uint32_t a0, uint32_t a1, uint32_t a2, uint32_t a3,
    uint32_t b0, uint32_t b1)
{
    asm volatile(
        "mma.sync.aligned.m16n8k16.row.col.f32.f16.f16.f32 "
        "{%0,%1,%2,%3}, {%4,%5,%6,%7}, {%8,%9}, {%0,%1,%2,%3};\n"
        : "+f"(c[0]), "+f"(c[1]), "+f"(c[2]), "+f"(c[3])
        : "r"(a0), "r"(a1), "r"(a2), "r"(a3), "r"(b0), "r"(b1));
}

__device__ __forceinline__ void ldsm4(uint32_t* r, uint32_t a) {
    asm volatile("ldmatrix.sync.aligned.m8n8.x4.shared.b16 {%0,%1,%2,%3}, [%4];"
        : "=r"(r[0]), "=r"(r[1]), "=r"(r[2]), "=r"(r[3]) : "r"(a));
}
__device__ __forceinline__ void ldsm4t(uint32_t* r, uint32_t a) {
    asm volatile("ldmatrix.sync.aligned.m8n8.x4.trans.shared.b16 {%0,%1,%2,%3}, [%4];"
        : "=r"(r[0]), "=r"(r[1]), "=r"(r[2]), "=r"(r[3]) : "r"(a));
}

__device__ __forceinline__ void cp16(uint32_t dst, const void* src) {
    asm volatile("cp.async.ca.shared.global [%0], [%1], 16;\n"
                 :: "r"(dst), "l"(src));
}

__device__ __forceinline__ float gelu_exact(float v) {
    return 0.5f * v * (1.0f + erff(v * 0.70710678118654752440f));
}

__device__ __forceinline__ float4 ld4h(const void* p, size_t elem) {
    uint2 t = *(const uint2*)((const __half*)p + elem);
    float2 a = __half22float2(*(__half2*)&t.x);
    float2 b = __half22float2(*(__half2*)&t.y);
    float4 v; v.x = a.x; v.y = a.y; v.z = b.x; v.w = b.y;
    return v;
}

// ---------------- weight transposes (two launches; shifts ncu capture to QKV) --
__global__ __launch_bounds__(256) void transpose_qo(
    const float* __restrict__ Wqkv, const float* __restrict__ Wo,
    __half* __restrict__ oqkv, __half* __restrict__ oo)
{
    __shared__ float t[32][33];
    int tb = blockIdx.x;
    const float* in; __half* out; int R, C, txw;
    if (tb < 3072) { in = Wqkv; out = oqkv; R = 1024; C = 3072; txw = 96; }
    else           { tb -= 3072; in = Wo; out = oo; R = 1024; C = 1024; txw = 32; }
    int bx = (tb % txw) * 32, by = (tb / txw) * 32;
    int x = threadIdx.x & 31, y = threadIdx.x >> 5;
    #pragma unroll
    for (int i = 0; i < 32; i += 8)
        t[y + i][x] = in[(size_t)(by + y + i) * C + bx + x];
    __syncthreads();
    #pragma unroll
    for (int i = 0; i < 32; i += 8)
        out[(size_t)(bx + y + i) * R + by + x] = __float2half_rn(t[x][y + i]);
}

__global__ __launch_bounds__(256) void transpose_w12(
    const float* __restrict__ W1, const float* __restrict__ W2,
    __half* __restrict__ o1, __half* __restrict__ o2)
{
    __shared__ float t[32][33];
    int tb = blockIdx.x;
    const float* in; __half* out; int R, C, txw;
    if (tb < 4096) { in = W1; out = o1; R = 1024; C = 4096; txw = 128; }
    else           { tb -= 4096; in = W2; out = o2; R = 4096; C = 1024; txw = 32; }
    int bx = (tb % txw) * 32, by = (tb / txw) * 32;
    int x = threadIdx.x & 31, y = threadIdx.x >> 5;
    #pragma unroll
    for (int i = 0; i < 32; i += 8)
        t[y + i][x] = in[(size_t)(by + y + i) * C + bx + x];
    __syncthreads();
    #pragma unroll
    for (int i = 0; i < 32; i += 8)
        out[(size_t)(bx + y + i) * R + by + x] = __float2half_rn(t[x][y + i]);
}

// ---------------- LayerNorm -> fp16 out ----------------
__global__ __launch_bounds__(256) void ln_kernel(
    const float* __restrict__ x, const float* __restrict__ g,
    const float* __restrict__ b, __half* __restrict__ outp)
{
    int row = blockIdx.x;
    int tid = threadIdx.x;
    const float4 v = ((const float4*)(x + (size_t)row * DM))[tid];
    float s  = v.x + v.y + v.z + v.w;
    float sq = v.x * v.x + v.y * v.y + v.z * v.z + v.w * v.w;
    #pragma unroll
    for (int o = 16; o; o >>= 1) {
        s  += __shfl_xor_sync(0xffffffffu, s,  o);
        sq += __shfl_xor_sync(0xffffffffu, sq, o);
    }
    __shared__ float ss[8], ssq[8];
    __shared__ float mean_s, inv_s;
    int w = tid >> 5, l = tid & 31;
    if (l == 0) { ss[w] = s; ssq[w] = sq; }
    __syncthreads();
    if (tid == 0) {
        float st = 0.f, sqt = 0.f;
        #pragma unroll
        for (int i = 0; i < 8; i++) { st += ss[i]; sqt += ssq[i]; }
        float mean = st * (1.0f / DM);
        float var  = sqt * (1.0f / DM) - mean * mean;
        mean_s = mean;
        inv_s  = rsqrtf(var + LN_EPS);
    }
    __syncthreads();
    float mean = mean_s, inv = inv_s;
    const float4 gv = ((const float4*)g)[tid];
    const float4 bv = ((const float4*)b)[tid];
    float o0 = (v.x - mean) * inv * gv.x + bv.x;
    float o1 = (v.y - mean) * inv * gv.y + bv.y;
    float o2 = (v.z - mean) * inv * gv.z + bv.z;
    float o3 = (v.w - mean) * inv * gv.w + bv.w;
    uint32_t* o16 = (uint32_t*)outp;
    size_t wi = ((size_t)row * DM + tid * 4) >> 1;
    o16[wi]     = packh(o1, o0);
    o16[wi + 1] = packh(o3, o2);
}

// ---------------- unified fp16 GEMM: TM x TN tiles ----------------
// MODE 3: QKV -> fp16 q/k/v bufs   MODE 4: gelu(+bias) -> fp16
// MODE 5: +bias+res(fp32) -> fp32
// (256,256): GS=3, 197KB, 1 CTA/SM.   (128,128): GS=3, 99KB, 2 CTAs/SM.
#define GS        3
#define G_BASE    1024
#define G_SMEM_T(TM, TN) (G_BASE + GS * ((TM) * 128 + (TN) * 128))

#if GEMM_TC
__device__ __forceinline__ bool elect_one() {
    uint32_t pred;
    asm volatile(
        "{\n\t.reg .pred p;\n\t"
        "elect.sync _|p, 0xFFFFFFFF;\n\t"
        "selp.b32 %0, 1, 0, p;\n\t}"
        : "=r"(pred));
    return pred != 0;
}
__device__ __forceinline__ uint64_t make_desc(uint32_t addr) {
    const uint64_t base = (2ULL << 61) | (1ULL << 46) | (64ULL << 32) | (1ULL << 16);
    return base | ((uint64_t)(addr >> 4) & 0x3FFF);
}
__device__ __forceinline__ void tc_mma_f16_ss(uint32_t d, uint64_t ad, uint64_t bd,
                                              uint32_t idesc, bool acc)
{
    uint32_t en = acc ? 1u : 0u;
    asm volatile(
        "{\n\t.reg .pred p;\n\t"
        "setp.ne.u32 p, %4, 0;\n\t"
        "tcgen05.mma.cta_group::1.kind::f16 [%0], %1, %2, %3, {%5, %5, %5, %5}, p;\n\t}"
        :: "r"(d), "l"(ad), "l"(bd), "r"(idesc), "r"(en), "r"(0u)
        : "memory");
}
#define MBAR_INIT(a, c) \
    asm volatile("mbarrier.init.shared.b64 [%0], %1;" :: "r"(a), "r"(c) : "memory")
#define MBAR_WAIT(a, par) do { \
    uint32_t _m = (a), _p = (par), _d; \
    asm volatile("{\n\t.reg .pred p;\n\t" \
        "mbarrier.try_wait.parity.acquire.cta.shared::cta.b64 p, [%1], %2;\n\t" \
        "selp.b32 %0, 1, 0, p;\n\t}" : "=r"(_d) : "r"(_m), "r"(_p) : "memory"); \
    if (!_d) { \
        asm volatile("{\n\t.reg .pred P1;\n\t" \
            "WL_%=:\n\t" \
            "mbarrier.try_wait.parity.acquire.cta.shared::cta.b64 P1, [%0], %1, 0x989680;\n\t" \
            "@P1 bra.uni WD_%=;\n\t" \
            "bra.uni WL_%=;\n\t" \
            "WD_%=:\n\t}" :: "r"(_m), "r"(_p) : "memory"); \
    } \
} while (0)
#define CPASYNC_MBAR_ARRIVE_NOINC(a) \
    asm volatile("cp.async.mbarrier.arrive.noinc.shared.b64 [%0];" :: "r"(a) : "memory")
#endif  // GEMM_TC

// epilogue write helper for MODE 3 (pair of adjacent columns, one row)
__device__ __forceinline__ void qkv_write_pair(int n, int row, float v0, float v1) {
    if (n < 1024) {
        int hd = n >> 6, d = n & 63;
        ((uint32_t*)g_q16)[(((size_t)hd * T_SEQ + row) * 64 + d) >> 1]
            = packh(v1 * QSCALE, v0 * QSCALE);
    } else if (n < 2048) {
        int hd = (n - 1024) >> 6, d = (n - 1024) & 63;
        ((uint32_t*)g_k16)[(((size_t)hd * T_SEQ + row) * 64 + d) >> 1]
            = packh(v1, v0);
    } else {
        int hd = (n - 2048) >> 6, d = (n - 2048) & 63;
        ((uint32_t*)g_v16)[(((size_t)hd * T_SEQ + row) * 64 + d) >> 1]
            = packh(v1, v0);
    }
}

template<int MODE, int TM, int TN>
__global__ __launch_bounds__(256, 2)
void gemm_any(const __half* __restrict__ A, const __half* __restrict__ Bt,
              const float* __restrict__ bias, const float* __restrict__ res,
              float* __restrict__ C, int M, int N, int K)
{
    extern __shared__ __align__(1024) char gsm[];
    const int tid = threadIdx.x, wid = tid >> 5, lane = tid & 31;

#if GEMM_TC
    constexpr int A_TILE = TM * 128;
    constexpr int B_TILE = TN * 128;
    constexpr int STAGE  = A_TILE + B_TILE;
    constexpr int TCOLS  = (TM == 256) ? 2 * TN : TN;
    const int m0 = blockIdx.y * TM, n0 = blockIdx.x * TN;
    const uint32_t sb = (uint32_t)__cvta_generic_to_shared(gsm);
    const uint32_t mb0 = sb + 16, mb1 = sb + 24;
    const uint32_t fmb = sb + 32;

    if (wid == 0) {
        asm volatile("tcgen05.alloc.cta_group::1.sync.aligned.shared::cta.b32 [%0], %1;"
                     :: "r"(sb), "r"((uint32_t)TCOLS) : "memory");
        asm volatile("tcgen05.relinquish_alloc_permit.cta_group::1.sync.aligned;");
    }
    if (tid == 0) {
        MBAR_INIT(mb0, 1); MBAR_INIT(mb1, 1);
        MBAR_INIT(fmb + 0, 256); MBAR_INIT(fmb + 8, 256); MBAR_INIT(fmb + 16, 256);
    }
    __syncthreads();
    uint32_t tb;
    asm volatile("ld.shared.b32 %0, [%1];" : "=r"(tb) : "r"(sb));

    const int KT = K >> 6;
    const size_t rowB = (size_t)K * 2;

    auto fill = [&](int slot, int ktile) {
        uint32_t s = sb + G_BASE + slot * STAGE;
        const char* Ab = (const char*)A + ((size_t)m0 * K + (size_t)ktile * 64) * 2;
        const char* Bb = (const char*)Bt + ((size_t)n0 * K + (size_t)ktile * 64) * 2;
        #pragma unroll
        for (int i = 0; i < TM / 32; i++) {
            int idx = tid + i * 256;
            int r = idx >> 3, ch = (idx & 7) * 16;
            uint32_t byte = (uint32_t)(r * 128 + ch);
            uint32_t sw = byte ^ ((byte >> 3) & 0x70);
            cp16(s + sw, Ab + (size_t)r * rowB + ch);
        }
        #pragma unroll
        for (int i = 0; i < TN / 32; i++) {
            int idx = tid + i * 256;
            int r = idx >> 3, ch = (idx & 7) * 16;
            uint32_t byte = (uint32_t)(r * 128 + ch);
            uint32_t sw = byte ^ ((byte >> 3) & 0x70);
            cp16(s + A_TILE + sw, Bb + (size_t)r * rowB + ch);
        }
        CPASYNC_MBAR_ARRIVE_NOINC(fmb + slot * 8);
    };

    #pragma unroll
    for (int st = 0; st < GS - 1; st++) fill(st, st);

    const uint32_t idesc = (1u << 4) | (0u << 7) | (0u << 10)
                         | ((uint32_t)(TN / 8) << 17) | (8u << 24);

    int ph0 = 0, ph1 = 0;
    for (int kt = 0; kt < KT; kt++) {
        if (wid == 0) {
            int slot = kt % GS;
            int fph = (kt / GS) & 1;
            MBAR_WAIT(fmb + slot * 8, fph);
            asm volatile("fence.proxy.async.shared::cta;" ::: "memory");
            if (elect_one()) {
                uint32_t s = sb + G_BASE + slot * STAGE;
                uint64_t ad = make_desc(s);
                uint64_t bd = make_desc(s + A_TILE);
                #pragma unroll
                for (int ks = 0; ks < 4; ks++) {
                    bool acc = (kt > 0) || (ks > 0);
                    tc_mma_f16_ss(tb, ad + ks * 2, bd + ks * 2, idesc, acc);
                    if (TM == 256)
                        tc_mma_f16_ss(tb + TN, ad + 1024 + ks * 2, bd + ks * 2, idesc, acc);
                }
                uint32_t mb = (kt & 1) ? mb1 : mb0;
                asm volatile(
                    "tcgen05.commit.cta_group::1.mbarrier::arrive::one.shared::cluster.b64 [%0];"
                    :: "r"(mb) : "memory");
            }
        }

        if (kt >= 1) {
            if ((kt - 1) & 1) { MBAR_WAIT(mb1, ph1); ph1 ^= 1; }
            else              { MBAR_WAIT(mb0, ph0); ph0 ^= 1; }
        }
        if (kt + GS - 1 < KT) fill((kt + GS - 1) % GS, kt + GS - 1);
    }

    if ((KT - 1) & 1) { MBAR_WAIT(mb1, ph1); }
    else              { MBAR_WAIT(mb0, ph0); }
    asm volatile("tcgen05.fence::after_thread_sync;" ::: "memory");

    {
        int row; uint32_t dbase; int cstart;
        if (TM == 256) {
            row = m0 + ((wid < 4) ? wid * 32 : 128 + (wid - 4) * 32) + lane;
            dbase = tb + ((wid < 4) ? 0u : (uint32_t)TN);
            cstart = 0;
        } else {
            row = m0 + (wid & 3) * 32 + lane;
            dbase = tb;
            cstart = (wid < 4) ? 0 : TN / 2;
        }
        const int cspan = (TM == 256) ? TN : TN / 2;
        #pragma unroll
        for (int ci = 0; ci < 256; ci += 32) {
            if (ci >= cspan) break;
            const int c0 = cstart + ci;
            float d[32];
            asm volatile(
                "tcgen05.ld.sync.aligned.32x32b.x32.b32 "
                "{%0,%1,%2,%3,%4,%5,%6,%7,%8,%9,%10,%11,%12,%13,%14,%15,"
                "%16,%17,%18,%19,%20,%21,%22,%23,%24,%25,%26,%27,%28,%29,%30,%31}, [%32];"
                : "=f"(d[0]),  "=f"(d[1]),  "=f"(d[2]),  "=f"(d[3]),
                  "=f"(d[4]),  "=f"(d[5]),  "=f"(d[6]),  "=f"(d[7]),
                  "=f"(d[8]),  "=f"(d[9]),  "=f"(d[10]), "=f"(d[11]),
                  "=f"(d[12]), "=f"(d[13]), "=f"(d[14]), "=f"(d[15]),
                  "=f"(d[16]), "=f"(d[17]), "=f"(d[18]), "=f"(d[19]),
                  "=f"(d[20]), "=f"(d[21]), "=f"(d[22]), "=f"(d[23]),
                  "=f"(d[24]), "=f"(d[25]), "=f"(d[26]), "=f"(d[27]),
                  "=f"(d[28]), "=f"(d[29]), "=f"(d[30]), "=f"(d[31])
                : "r"(dbase + c0));
            asm volatile("tcgen05.wait::ld.sync.aligned;" ::: "memory");

            #pragma unroll
            for (int c = 0; c < 32; c += 4) {
                const int n = n0 + c0 + c;
                const float4 bv = *(const float4*)(bias + n);
                float4 v;
                v.x = d[c + 0] + bv.x; v.y = d[c + 1] + bv.y;
                v.z = d[c + 2] + bv.z; v.w = d[c + 3] + bv.w;
                if (MODE == 3) {
                    qkv_write_pair(n,     row, v.x, v.y);
                    qkv_write_pair(n + 2, row, v.z, v.w);
                } else if (MODE == 4) {
                    uint32_t* o16 = (uint32_t*)g_ff16;
                    size_t wi = ((size_t)row * N + n) >> 1;
                    o16[wi]     = packh(gelu_exact(v.y), gelu_exact(v.x));
                    o16[wi + 1] = packh(gelu_exact(v.w), gelu_exact(v.z));
                } else {
                    const float4 rv = *(const float4*)(res + (size_t)row * N + n);
                    v.x += rv.x; v.y += rv.y; v.z += rv.z; v.w += rv.w;
                    *(float4*)(C + (size_t)row * N + n) = v;
                }
            }
        }
    }

    __syncthreads();
    if (tid == 0) {
        asm volatile("mbarrier.inval.shared.b64 [%0];" :: "r"(mb0) : "memory");
        asm volatile("mbarrier.inval.shared.b64 [%0];" :: "r"(mb1) : "memory");
        asm volatile("mbarrier.inval.shared.b64 [%0];" :: "r"(fmb + 0) : "memory");
        asm volatile("mbarrier.inval.shared.b64 [%0];" :: "r"(fmb + 8) : "memory");
        asm volatile("mbarrier.inval.shared.b64 [%0];" :: "r"(fmb + 16) : "memory");
    }
    __syncthreads();
    if (wid == 0)
        asm volatile("tcgen05.dealloc.cta_group::1.sync.aligned.b32 %0, %1;"
                     :: "r"(tb), "r"((uint32_t)TCOLS));

#else
    // ================= mma.sync fp16 fallback: (TM/128)x(TN/128) subtiles =========
    float* As = (float*)gsm;
    float* Bs = As + 2 * 16 * 132;
    #define AS(buf, k, m) As[((buf) * 16 + (k)) * 132 + (m)]
    #define BS(buf, k, n) Bs[((buf) * 16 + (k)) * 132 + (n)]

    const int wm = wid >> 2, wn = wid & 3;
    const int gp = lane >> 2, tg = lane & 3;

    for (int mi = 0; mi < TM / 128; mi++)
    for (int ni = 0; ni < TN / 128; ni++) {
        const int m0 = blockIdx.y * TM + mi * 128;
        const int n0 = blockIdx.x * TN + ni * 128;

        float c[4][4][4];
        #pragma unroll
        for (int i = 0; i < 4; i++)
            #pragma unroll
            for (int j = 0; j < 4; j++)
                #pragma unroll
                for (int r = 0; r < 4; r++) c[i][j][r] = 0.f;

        const int KT = K >> 4;
        float4 va[2], vb[2];

        __syncthreads();
        #pragma unroll
        for (int i = 0; i < 2; i++) {
            int idx = tid + i * 256;
            int r = idx >> 2, c4 = (idx & 3) << 2;
            va[i] = ld4h(A,  (size_t)(m0 + r) * K + c4);
            vb[i] = ld4h(Bt, (size_t)(n0 + r) * K + c4);
        }
        #pragma unroll
        for (int i = 0; i < 2; i++) {
            int idx = tid + i * 256;
            int r = idx >> 2, c4 = (idx & 3) << 2;
            AS(0, c4 + 0, r) = va[i].x; AS(0, c4 + 1, r) = va[i].y;
            AS(0, c4 + 2, r) = va[i].z; AS(0, c4 + 3, r) = va[i].w;
            BS(0, c4 + 0, r) = vb[i].x; BS(0, c4 + 1, r) = vb[i].y;
            BS(0, c4 + 2, r) = vb[i].z; BS(0, c4 + 3, r) = vb[i].w;
        }
        __syncthreads();

        int cur = 0;
        for (int kt = 0; kt < KT; kt++) {
            if (kt + 1 < KT) {
                #pragma unroll
                for (int i = 0; i < 2; i++) {
                    int idx = tid + i * 256;
                    int r = idx >> 2, c4 = (idx & 3) << 2;
                    va[i] = ld4h(A,  (size_t)(m0 + r) * K + (kt + 1) * 16 + c4);
                    vb[i] = ld4h(Bt, (size_t)(n0 + r) * K + (kt + 1) * 16 + c4);
                }
            }
            {
                uint32_t a[4][4], b[4][2];
                #pragma unroll
                for (int mf = 0; mf < 4; mf++) {
                    int r0 = wm * 64 + mf * 16;
                    a[mf][0] = packh(AS(cur, 2*tg+1, r0 + gp    ), AS(cur, 2*tg,   r0 + gp    ));
                    a[mf][1] = packh(AS(cur, 2*tg+1, r0 + gp + 8), AS(cur, 2*tg,   r0 + gp + 8));
                    a[mf][2] = packh(AS(cur, 2*tg+9, r0 + gp    ), AS(cur, 2*tg+8, r0 + gp    ));
                    a[mf][3] = packh(AS(cur, 2*tg+9, r0 + gp + 8), AS(cur, 2*tg+8, r0 + gp + 8));
                }
                #pragma unroll
                for (int nf = 0; nf < 4; nf++) {
                    int c0 = wn * 32 + nf * 8;
                    b[nf][0] = packh(BS(cur, 2*tg+1, c0 + gp), BS(cur, 2*tg,   c0 + gp));
                    b[nf][1] = packh(BS(cur, 2*tg+9, c0 + gp), BS(cur, 2*tg+8, c0 + gp));
                }
                #pragma unroll
                for (int mf = 0; mf < 4; mf++)
                    #pragma unroll
                    for (int nf = 0; nf < 4; nf++)
                        mma_f16(c[mf][nf], a[mf][0], a[mf][1], a[mf][2], a[mf][3],
                                b[nf][0], b[nf][1]);
            }
            if (kt + 1 < KT) {
                int nxt = cur ^ 1;
                #pragma unroll
                for (int i = 0; i < 2; i++) {
                    int idx = tid + i * 256;
                    int r = idx >> 2, c4 = (idx & 3) << 2;
                    AS(nxt, c4 + 0, r) = va[i].x; AS(nxt, c4 + 1, r) = va[i].y;
                    AS(nxt, c4 + 2, r) = va[i].z; AS(nxt, c4 + 3, r) = va[i].w;
                    BS(nxt, c4 + 0, r) = vb[i].x; BS(nxt, c4 + 1, r) = vb[i].y;
                    BS(nxt, c4 + 2, r) = vb[i].z; BS(nxt, c4 + 3, r) = vb[i].w;
                }
                __syncthreads();
                cur = nxt;
            }
        }

        #pragma unroll
        for (int mf = 0; mf < 4; mf++) {
            #pragma unroll
            for (int nf = 0; nf < 4; nf++) {
                int col = n0 + wn * 32 + nf * 8 + 2 * tg;
                float bi0 = bias[col], bi1 = bias[col + 1];
                #pragma unroll
                for (int hh = 0; hh < 2; hh++) {
                    int row = m0 + wm * 64 + mf * 16 + gp + hh * 8;
                    float v0 = c[mf][nf][hh * 2 + 0] + bi0;
                    float v1 = c[mf][nf][hh * 2 + 1] + bi1;
                    if (MODE == 3) {
                        qkv_write_pair(col, row, v0, v1);
                    } else if (MODE == 4) {
                        ((uint32_t*)g_ff16)[((size_t)row * N + col) >> 1]
                            = packh(gelu_exact(v1), gelu_exact(v0));
                    } else {
                        const float2 rv = *(const float2*)(res + (size_t)row * N + col);
                        v0 += rv.x; v1 += rv.y;
                        float2 o; o.x = v0; o.y = v1;
                        *(float2*)(C + (size_t)row * N + col) = o;
                    }
                }
            }
        }
    }
    #undef AS
    #undef BS
#endif
}

// ---------------- causal flash attention (unchanged R15 winner) --------------
#define AQ_OFF  0
#define AK_OFF  4608
#define AV_OFF  9216
#define AM_OFF  13824
#define ATTN_SMEM ((13824 + 128) * 4)   // 55808

__global__ __launch_bounds__(256, 2) void attn_kernel(
    const int* __restrict__ amask, __half* __restrict__ y)
{
    extern __shared__ uint32_t shw[];
    uint32_t* Qs = shw + AQ_OFF;
    uint32_t* Ks = shw + AK_OFF;
    uint32_t* Vs = shw + AV_OFF;
    int*      mk = (int*)(shw + AM_OFF);

    const int tid = threadIdx.x, lane = tid & 31, w = tid >> 5;
    const int gp = lane >> 2, tg = lane & 3;
    const int h = blockIdx.y;
    const int q0 = (gridDim.x - 1 - blockIdx.x) * 128;
    const int qw = q0 + w * 16;

    const int lm = lane >> 3, lr = lane & 7;
    const uint32_t koff = (uint32_t)(((lm >> 1) * 8 + lr) * 144 + (lm & 1) * 16);
    const uint32_t voff = (uint32_t)(((lm & 1) * 8 + lr) * 144 + (lm >> 1) * 16);
    const uint32_t Kb = (uint32_t)__cvta_generic_to_shared(Ks);
    const uint32_t Vb = (uint32_t)__cvta_generic_to_shared(Vs);

    {
        const __half* qb = g_q16 + ((size_t)h * T_SEQ + q0) * 64;
        #pragma unroll
        for (int i = 0; i < 4; i++) {
            int idx = tid + i * 256;
            int r = idx >> 3, ch = idx & 7;
            cp16((uint32_t)__cvta_generic_to_shared(Qs + r * 36 + ch * 4),
                 qb + (size_t)r * 64 + ch * 8);
        }
    }
    asm volatile("cp.async.commit_group;" ::: "memory");

    if (tid < 128) {
        int buf = tid >> 6, r = tid & 63;
        uint32_t* vr = Vs + buf * 2304 + r * 36;
        vr[32] = 0x00003C00u; vr[33] = 0u; vr[34] = 0u; vr[35] = 0u;
    }

    auto fill_kv = [&](int buf, int kt) {
        const __half* kbs = g_k16 + ((size_t)h * T_SEQ + kt * 64) * 64;
        const __half* vbs = g_v16 + ((size_t)h * T_SEQ + kt * 64) * 64;
        #pragma unroll
        for (int i = 0; i < 2; i++) {
            int idx = tid + i * 256;
            int r = idx >> 3, ch = idx & 7;
            cp16((uint32_t)__cvta_generic_to_shared(Ks + buf * 2304 + r * 36 + ch * 4),
                 kbs + (size_t)r * 64 + ch * 8);
            cp16((uint32_t)__cvta_generic_to_shared(Vs + buf * 2304 + r * 36 + ch * 4),
                 vbs + (size_t)r * 64 + ch * 8);
        }
        if (tid < 16)
            cp16((uint32_t)__cvta_generic_to_shared(mk + buf * 64 + tid * 4),
                 amask + kt * 64 + tid * 4);
    };

    fill_kv(0, 0);
    asm volatile("cp.async.commit_group;" ::: "memory");
    asm volatile("cp.async.wait_group 0;" ::: "memory");
    __syncthreads();

    uint32_t qa[4][4];
    {
        int r0 = w * 16;
        #pragma unroll
        for (int ks = 0; ks < 4; ks++) {
            qa[ks][0] = Qs[(r0 + gp    ) * 36 + 8 * ks + tg    ];
            qa[ks][1] = Qs[(r0 + gp + 8) * 36 + 8 * ks + tg    ];
            qa[ks][2] = Qs[(r0 + gp    ) * 36 + 8 * ks + 4 + tg];
            qa[ks][3] = Qs[(r0 + gp + 8) * 36 + 8 * ks + 4 + tg];
        }
    }

    float m0 = -INFINITY, m1 = -INFINITY;
    float o[9][4];
    #pragma unroll
    for (int nf = 0; nf < 9; nf++)
        #pragma unroll
        for (int r = 0; r < 4; r++) o[nf][r] = 0.f;

    const uint32_t onesb = (gp == 0) ? 0x3C003C00u : 0u;

    const int ktmax = (q0 + 127) >> 6;
    const int kdiag = q0 >> 6;
    const int row0 = qw + gp, row1 = qw + gp + 8;
    int cur = 0;

    for (int kt = 0; kt <= ktmax; kt++) {
        asm volatile("cp.async.wait_group 0;" ::: "memory");
        __syncthreads();

        if (kt < ktmax) {
            fill_kv(cur ^ 1, kt + 1);
            asm volatile("cp.async.commit_group;" ::: "memory");
        }

        const uint32_t Kcur = Kb + cur * 9216;
        const uint32_t Vcur = Vb + cur * 9216;
        const int*     M    = mk + cur * 64;
        const bool diag = (kt >= kdiag);

        float sc[8][4];
        #pragma unroll
        for (int nf = 0; nf < 8; nf++)
            #pragma unroll
            for (int r = 0; r < 4; r++) sc[nf][r] = 0.f;

        #pragma unroll
        for (int ks = 0; ks < 4; ks++) {
            #pragma unroll
            for (int j = 0; j < 4; j++) {
                uint32_t kb[4];
                ldsm4(kb, Kcur + j * 2304 + ks * 32 + koff);
                mma_f16(sc[2*j],   qa[ks][0], qa[ks][1], qa[ks][2], qa[ks][3], kb[0], kb[1]);
                mma_f16(sc[2*j+1], qa[ks][0], qa[ks][1], qa[ks][2], qa[ks][3], kb[2], kb[3]);
            }
        }

        float tm0 = -INFINITY, tm1 = -INFINITY;
        if (diag) {
            #pragma unroll
            for (int nf = 0; nf < 8; nf++) {
                int cl = nf * 8 + 2 * tg;
                int c  = kt * 64 + cl;
                bool mk0 = M[cl] != 0, mk1 = M[cl + 1] != 0;
                float s0 = sc[nf][0], s1 = sc[nf][1];
                float s2 = sc[nf][2], s3 = sc[nf][3];
                s0 = (c     <= row0 && mk0) ? s0 : -INFINITY;
                s1 = (c + 1 <= row0 && mk1) ? s1 : -INFINITY;
                s2 = (c     <= row1 && mk0) ? s2 : -INFINITY;
                s3 = (c + 1 <= row1 && mk1) ? s3 : -INFINITY;
                sc[nf][0] = s0; sc[nf][1] = s1; sc[nf][2] = s2; sc[nf][3] = s3;
                tm0 = fmaxf(tm0, fmaxf(s0, s1));
                tm1 = fmaxf(tm1, fmaxf(s2, s3));
            }
        } else {
            #pragma unroll
            for (int nf = 0; nf < 8; nf++) {
                int cl = nf * 8 + 2 * tg;
                bool mk0 = M[cl] != 0, mk1 = M[cl + 1] != 0;
                float s0 = mk0 ? sc[nf][0] : -INFINITY;
                float s1 = mk1 ? sc[nf][1] : -INFINITY;
                float s2 = mk0 ? sc[nf][2] : -INFINITY;
                float s3 = mk1 ? sc[nf][3] : -INFINITY;
                sc[nf][0] = s0; sc[nf][1] = s1; sc[nf][2] = s2; sc[nf][3] = s3;
                tm0 = fmaxf(tm0, fmaxf(s0, s1));
                tm1 = fmaxf(tm1, fmaxf(s2, s3));
            }
        }
        tm0 = fmaxf(tm0, __shfl_xor_sync(0xffffffffu, tm0, 1));
        tm0 = fmaxf(tm0, __shfl_xor_sync(0xffffffffu, tm0, 2));
        tm1 = fmaxf(tm1, __shfl_xor_sync(0xffffffffu, tm1, 1));
        tm1 = fmaxf(tm1, __shfl_xor_sync(0xffffffffu, tm1, 2));

        float nm0 = fmaxf(m0, tm0), nm1 = fmaxf(m1, tm1);
        float ne0 = fmaxf(nm0, -1e30f), ne1 = fmaxf(nm1, -1e30f);
        float al0 = ex2(m0 - ne0), al1 = ex2(m1 - ne1);
        m0 = nm0; m1 = nm1;

        #pragma unroll
        for (int nf = 0; nf < 9; nf++) {
            o[nf][0] *= al0; o[nf][1] *= al0;
            o[nf][2] *= al1; o[nf][3] *= al1;
        }

        #pragma unroll
        for (int ks = 0; ks < 4; ks++) {
            uint32_t pa0 = ex2h2(packh(sc[2*ks  ][1] - ne0, sc[2*ks  ][0] - ne0));
            uint32_t pa1 = ex2h2(packh(sc[2*ks  ][3] - ne1, sc[2*ks  ][2] - ne1));
            uint32_t pa2 = ex2h2(packh(sc[2*ks+1][1] - ne0, sc[2*ks+1][0] - ne0));
            uint32_t pa3 = ex2h2(packh(sc[2*ks+1][3] - ne1, sc[2*ks+1][2] - ne1));
            #pragma unroll
            for (int j = 0; j < 4; j++) {
                uint32_t vb[4];
                ldsm4t(vb, Vcur + ks * 2304 + j * 32 + voff);
                mma_f16(o[2*j],   pa0, pa1, pa2, pa3, vb[0], vb[1]);
                mma_f16(o[2*j+1], pa0, pa1, pa2, pa3, vb[2], vb[3]);
            }
            mma_f16(o[8], pa0, pa1, pa2, pa3, onesb, onesb);
        }
        cur ^= 1;
    }

    float l0 = __shfl_sync(0xffffffffu, o[8][0], lane & ~3);
    float l1 = __shfl_sync(0xffffffffu, o[8][2], lane & ~3);
    float il0 = 1.0f / fmaxf(l0, 1e-30f);
    float il1 = 1.0f / fmaxf(l1, 1e-30f);
    uint32_t* yw = (uint32_t*)y;
    #pragma unroll
    for (int nf = 0; nf < 8; nf++) {
        int col = h * HDIM + nf * 8 + 2 * tg;
        yw[((size_t)row0 * DM + col) >> 1] = packh(o[nf][1] * il0, o[nf][0] * il0);
        yw[((size_t)row1 * DM + col) >> 1] = packh(o[nf][3] * il1, o[nf][2] * il1);
    }
}

// ---------------- launcher ----------------
extern "C" void kernel_launch(void* const* d_in, const int* in_sizes, int n_in,
                              void* d_out, int out_size)
{
    const float* x     = (const float*)d_in[0];
    const int*   amask = (const int*)  d_in[1];
    const float* ln1g  = (const float*)d_in[2];
    const float* ln1b  = (const float*)d_in[3];
    const float* Wqkv  = (const float*)d_in[4];
    const float* bqkv  = (const float*)d_in[5];
    const float* Wo    = (const float*)d_in[6];
    const float* bo    = (const float*)d_in[7];
    const float* ln2g  = (const float*)d_in[8];
    const float* ln2b  = (const float*)d_in[9];
    const float* W1    = (const float*)d_in[10];
    const float* b1    = (const float*)d_in[11];
    const float* W2    = (const float*)d_in[12];
    const float* b2    = (const float*)d_in[13];
    float* out = (float*)d_out;

    void *p_x2, *p_wqkv, *p_wo, *p_w1, *p_w2, *p_ln16, *p_y16, *p_ff16;
    cudaGetSymbolAddress(&p_x2,   g_x2);
    cudaGetSymbolAddress(&p_wqkv, g_wqkv16);
    cudaGetSymbolAddress(&p_wo,   g_wo16);
    cudaGetSymbolAddress(&p_w1,   g_w1_16);
    cudaGetSymbolAddress(&p_w2,   g_w2_16);
    cudaGetSymbolAddress(&p_ln16, g_ln16);
    cudaGetSymbolAddress(&p_y16,  g_y16);
    cudaGetSymbolAddress(&p_ff16, g_ff16);

    cudaFuncSetAttribute(attn_kernel,
        cudaFuncAttributeMaxDynamicSharedMemorySize, ATTN_SMEM);
    cudaFuncSetAttribute(gemm_any<3, 256, 256>,
        cudaFuncAttributeMaxDynamicSharedMemorySize, G_SMEM_T(256, 256));
    cudaFuncSetAttribute(gemm_any<4, 256, 256>,
        cudaFuncAttributeMaxDynamicSharedMemorySize, G_SMEM_T(256, 256));
    cudaFuncSetAttribute(gemm_any<5, 128, 128>,
        cudaFuncAttributeMaxDynamicSharedMemorySize, G_SMEM_T(128, 128));

    // 0-1. weight transposes (two launches; puts QKV at capture idx 3)
    transpose_qo <<<4096, 256>>>(Wqkv, Wo, (__half*)p_wqkv, (__half*)p_wo);
    transpose_w12<<<8192, 256>>>(W1, W2, (__half*)p_w1, (__half*)p_w2);

    // 2. LN1 -> fp16
    ln_kernel<<<T_SEQ, 256>>>(x, ln1g, ln1b, (__half*)p_ln16);
    // 3. QKV (fp16) -> fp16 q/k/v buffers   [ncu capture lands here]
    gemm_any<3, 256, 256><<<dim3(12, 16), 256, G_SMEM_T(256, 256)>>>(
        (__half*)p_ln16, (__half*)p_wqkv, bqkv, nullptr, nullptr, T_SEQ, 3 * DM, DM);
    // 4. attention -> fp16 y
    attn_kernel<<<dim3(32, 16), 256, ATTN_SMEM>>>(amask, (__half*)p_y16);
    // 5. x2 = x + y @ W_o + b_o   (128x128 tiles, 256 CTAs, 2/SM)
    gemm_any<5, 128, 128><<<dim3(8, 32), 256, G_SMEM_T(128, 128)>>>(
        (__half*)p_y16, (__half*)p_wo, bo, x, (float*)p_x2, T_SEQ, DM, DM);
    // 6. LN2 -> fp16
    ln_kernel<<<T_SEQ, 256>>>((float*)p_x2, ln2g, ln2b, (__half*)p_ln16);
    // 7. FF1: gelu -> fp16 g_ff16
    gemm_any<4, 256, 256><<<dim3(16, 16), 256, G_SMEM_T(256, 256)>>>(
        (__half*)p_ln16, (__half*)p_w1, b1, nullptr, nullptr, T_SEQ, DFF, DM);
    // 8. FF2: out = x2 + ff @ W2 + b2   (128x128 tiles, 256 CTAs, 2/SM)
    gemm_any<5, 128, 128><<<dim3(8, 32), 256, G_SMEM_T(128, 128)>>>(
        (__half*)p_ff16, (__half*)p_w2, b2, (float*)p_x2, out, T_SEQ, DM, DFF);
}

// round 17
// speedup vs baseline: 1.0178x; 1.0178x over previous
#include <cuda_runtime.h>
#include <cuda_fp16.h>
#include <cstdint>
#include <math.h>

#define T_SEQ   4096
#define DM      1024
#define DFF     4096
#define NHEADS  16
#define HDIM    64
#define LN_EPS  1e-5f

// ---- arch-specific feature gate: tcgen05 only exists on sm_10xa/f targets ----
#if defined(__CUDA_ARCH__)
#  if defined(__CUDA_ARCH_FEAT_SM103_ALL) || defined(__CUDA_ARCH_FEAT_SM100_ALL) || defined(__CUDA_ARCH_FEAT_SM101_ALL)
#    define GEMM_TC 1
#  elif defined(__CUDA_ARCH_SPECIFIC__)
#    define GEMM_TC ((__CUDA_ARCH_SPECIFIC__ >= 1000) ? 1 : 0)
#  elif defined(__CUDA_ARCH_FAMILY_SPECIFIC__)
#    define GEMM_TC ((__CUDA_ARCH_FAMILY_SPECIFIC__ >= 1000) ? 1 : 0)
#  else
#    define GEMM_TC 0
#  endif
#else
#  define GEMM_TC 0
#endif

// ---------------- scratch (static device globals; no allocation) ----------------
static __device__ float g_x2 [T_SEQ * DM];           // residual after attn (fp32)
// fp16 weights [N,K] K-major
static __device__ __half g_wqkv16[3 * DM * DM];
static __device__ __half g_wo16  [DM * DM];
static __device__ __half g_w1_16 [DFF * DM];
static __device__ __half g_w2_16 [DM * DFF];
// fp16 activations
static __device__ __half g_ln16[T_SEQ * DM];   // LN1 out, then LN2 out (sequential reuse)
static __device__ __half g_y16 [T_SEQ * DM];   // attention out
static __device__ __half g_ff16[T_SEQ * DFF];  // gelu out
// fp16 attention operands written by the QKV GEMM epilogue, all [h][t][d]
static __device__ __half g_q16[NHEADS * T_SEQ * HDIM];   // scaled log2e/8
static __device__ __half g_k16[NHEADS * T_SEQ * HDIM];
static __device__ __half g_v16[NHEADS * T_SEQ * HDIM];

#define QSCALE 0.18033688011112042f   // (1/8) * log2(e)

// ---------------- helpers ----------------
__device__ __forceinline__ uint32_t packh(float hi, float lo) {
    uint32_t r;
    asm("cvt.rn.f16x2.f32 %0, %1, %2;" : "=r"(r) : "f"(hi), "f"(lo));
    return r;
}

__device__ __forceinline__ float ex2(float x) {
    float r;
    asm("ex2.approx.f32 %0, %1;" : "=f"(r) : "f"(x));
    return r;
}

__device__ __forceinline__ uint32_t ex2h2(uint32_t x) {
    uint32_t r;
    asm("ex2.approx.f16x2 %0, %1;" : "=r"(r) : "r"(x));
    return r;
}

__device__ __forceinline__ void mma_f16(float* c,
    uint32_t a0, uint32_t a1, uint32_t a2, uint32_t a3,
    uint32_t b0, uint32_t b1)
{
    asm volatile(
        "mma.sync.aligned.m16n8k16.row.col.f32.f16.f16.f32 "
        "{%0,%1,%2,%3}, {%4,%5,%6,%7}, {%8,%9}, {%0,%1,%2,%3};\n"
        : "+f"(c[0]), "+f"(c[1]), "+f"(c[2]), "+f"(c[3])
        : "r"(a0), "r"(a1), "r"(a2), "r"(a3), "r"(b0), "r"(b1));
}

__device__ __forceinline__ void ldsm4(uint32_t* r, uint32_t a) {
    asm volatile("ldmatrix.sync.aligned.m8n8.x4.shared.b16 {%0,%1,%2,%3}, [%4];"
        : "=r"(r[0]), "=r"(r[1]), "=r"(r[2]), "=r"(r[3]) : "r"(a));
}
__device__ __forceinline__ void ldsm4t(uint32_t* r, uint32_t a) {
    asm volatile("ldmatrix.sync.aligned.m8n8.x4.trans.shared.b16 {%0,%1,%2,%3}, [%4];"
        : "=r"(r[0]), "=r"(r[1]), "=r"(r[2]), "=r"(r[3]) : "r"(a));
}

__device__ __forceinline__ void cp16(uint32_t dst, const void* src) {
    asm volatile("cp.async.ca.shared.global [%0], [%1], 16;\n"
                 :: "r"(dst), "l"(src));
}

__device__ __forceinline__ float gelu_exact(float v) {
    return 0.5f * v * (1.0f + erff(v * 0.70710678118654752440f));
}

__device__ __forceinline__ float4 ld4h(const void* p, size_t elem) {
    uint2 t = *(const uint2*)((const __half*)p + elem);
    float2 a = __half22float2(*(__half2*)&t.x);
    float2 b = __half22float2(*(__half2*)&t.y);
    float4 v; v.x = a.x; v.y = a.y; v.z = b.x; v.w = b.y;
    return v;
}

// ---------------- weight transposes (two launches) ----------------
__global__ __launch_bounds__(256) void transpose_qo(
    const float* __restrict__ Wqkv, const float* __restrict__ Wo,
    __half* __restrict__ oqkv, __half* __restrict__ oo)
{
    __shared__ float t[32][33];
    int tb = blockIdx.x;
    const float* in; __half* out; int R, C, txw;
    if (tb < 3072) { in = Wqkv; out = oqkv; R = 1024; C = 3072; txw = 96; }
    else           { tb -= 3072; in = Wo; out = oo; R = 1024; C = 1024; txw = 32; }
    int bx = (tb % txw) * 32, by = (tb / txw) * 32;
    int x = threadIdx.x & 31, y = threadIdx.x >> 5;
    #pragma unroll
    for (int i = 0; i < 32; i += 8)
        t[y + i][x] = in[(size_t)(by + y + i) * C + bx + x];
    __syncthreads();
    #pragma unroll
    for (int i = 0; i < 32; i += 8)
        out[(size_t)(bx + y + i) * R + by + x] = __float2half_rn(t[x][y + i]);
}

__global__ __launch_bounds__(256) void transpose_w12(
    const float* __restrict__ W1, const float* __restrict__ W2,
    __half* __restrict__ o1, __half* __restrict__ o2)
{
    __shared__ float t[32][33];
    int tb = blockIdx.x;
    const float* in; __half* out; int R, C, txw;
    if (tb < 4096) { in = W1; out = o1; R = 1024; C = 4096; txw = 128; }
    else           { tb -= 4096; in = W2; out = o2; R = 4096; C = 1024; txw = 32; }
    int bx = (tb % txw) * 32, by = (tb / txw) * 32;
    int x = threadIdx.x & 31, y = threadIdx.x >> 5;
    #pragma unroll
    for (int i = 0; i < 32; i += 8)
        t[y + i][x] = in[(size_t)(by + y + i) * C + bx + x];
    __syncthreads();
    #pragma unroll
    for (int i = 0; i < 32; i += 8)
        out[(size_t)(bx + y + i) * R + by + x] = __float2half_rn(t[x][y + i]);
}

// ---------------- LayerNorm -> fp16 out ----------------
__global__ __launch_bounds__(256) void ln_kernel(
    const float* __restrict__ x, const float* __restrict__ g,
    const float* __restrict__ b, __half* __restrict__ outp)
{
    int row = blockIdx.x;
    int tid = threadIdx.x;
    const float4 v = ((const float4*)(x + (size_t)row * DM))[tid];
    float s  = v.x + v.y + v.z + v.w;
    float sq = v.x * v.x + v.y * v.y + v.z * v.z + v.w * v.w;
    #pragma unroll
    for (int o = 16; o; o >>= 1) {
        s  += __shfl_xor_sync(0xffffffffu, s,  o);
        sq += __shfl_xor_sync(0xffffffffu, sq, o);
    }
    __shared__ float ss[8], ssq[8];
    __shared__ float mean_s, inv_s;
    int w = tid >> 5, l = tid & 31;
    if (l == 0) { ss[w] = s; ssq[w] = sq; }
    __syncthreads();
    if (tid == 0) {
        float st = 0.f, sqt = 0.f;
        #pragma unroll
        for (int i = 0; i < 8; i++) { st += ss[i]; sqt += ssq[i]; }
        float mean = st * (1.0f / DM);
        float var  = sqt * (1.0f / DM) - mean * mean;
        mean_s = mean;
        inv_s  = rsqrtf(var + LN_EPS);
    }
    __syncthreads();
    float mean = mean_s, inv = inv_s;
    const float4 gv = ((const float4*)g)[tid];
    const float4 bv = ((const float4*)b)[tid];
    float o0 = (v.x - mean) * inv * gv.x + bv.x;
    float o1 = (v.y - mean) * inv * gv.y + bv.y;
    float o2 = (v.z - mean) * inv * gv.z + bv.z;
    float o3 = (v.w - mean) * inv * gv.w + bv.w;
    uint32_t* o16 = (uint32_t*)outp;
    size_t wi = ((size_t)row * DM + tid * 4) >> 1;
    o16[wi]     = packh(o1, o0);
    o16[wi + 1] = packh(o3, o2);
}

// ---------------- unified fp16 GEMM: 128 x 256 tiles, GS=2, 2 CTAs/SM --------
// MODE 3: QKV -> fp16 q/k/v bufs   MODE 4: gelu(+bias) -> fp16
// MODE 5: +bias+res(fp32) -> fp32
#define G_BASE    1024
#define G_SMEM_T(TM, TN, GSP) (G_BASE + (GSP) * ((TM) * 128 + (TN) * 128))

#if GEMM_TC
__device__ __forceinline__ bool elect_one() {
    uint32_t pred;
    asm volatile(
        "{\n\t.reg .pred p;\n\t"
        "elect.sync _|p, 0xFFFFFFFF;\n\t"
        "selp.b32 %0, 1, 0, p;\n\t}"
        : "=r"(pred));
    return pred != 0;
}
__device__ __forceinline__ uint64_t make_desc(uint32_t addr) {
    const uint64_t base = (2ULL << 61) | (1ULL << 46) | (64ULL << 32) | (1ULL << 16);
    return base | ((uint64_t)(addr >> 4) & 0x3FFF);
}
__device__ __forceinline__ void tc_mma_f16_ss(uint32_t d, uint64_t ad, uint64_t bd,
                                              uint32_t idesc, bool acc)
{
    uint32_t en = acc ? 1u : 0u;
    asm volatile(
        "{\n\t.reg .pred p;\n\t"
        "setp.ne.u32 p, %4, 0;\n\t"
        "tcgen05.mma.cta_group::1.kind::f16 [%0], %1, %2, %3, {%5, %5, %5, %5}, p;\n\t}"
        :: "r"(d), "l"(ad), "l"(bd), "r"(idesc), "r"(en), "r"(0u)
        : "memory");
}
#define MBAR_INIT(a, c) \
    asm volatile("mbarrier.init.shared.b64 [%0], %1;" :: "r"(a), "r"(c) : "memory")
#define MBAR_WAIT(a, par) do { \
    uint32_t _m = (a), _p = (par), _d; \
    asm volatile("{\n\t.reg .pred p;\n\t" \
        "mbarrier.try_wait.parity.acquire.cta.shared::cta.b64 p, [%1], %2;\n\t" \
        "selp.b32 %0, 1, 0, p;\n\t}" : "=r"(_d) : "r"(_m), "r"(_p) : "memory"); \
    if (!_d) { \
        asm volatile("{\n\t.reg .pred P1;\n\t" \
            "WL_%=:\n\t" \
            "mbarrier.try_wait.parity.acquire.cta.shared::cta.b64 P1, [%0], %1, 0x989680;\n\t" \
            "@P1 bra.uni WD_%=;\n\t" \
            "bra.uni WL_%=;\n\t" \
            "WD_%=:\n\t}" :: "r"(_m), "r"(_p) : "memory"); \
    } \
} while (0)
#define CPASYNC_MBAR_ARRIVE_NOINC(a) \
    asm volatile("cp.async.mbarrier.arrive.noinc.shared.b64 [%0];" :: "r"(a) : "memory")
#endif  // GEMM_TC

// epilogue write helper for MODE 3 (pair of adjacent columns, one row)
__device__ __forceinline__ void qkv_write_pair(int n, int row, float v0, float v1) {
    if (n < 1024) {
        int hd = n >> 6, d = n & 63;
        ((uint32_t*)g_q16)[(((size_t)hd * T_SEQ + row) * 64 + d) >> 1]
            = packh(v1 * QSCALE, v0 * QSCALE);
    } else if (n < 2048) {
        int hd = (n - 1024) >> 6, d = (n - 1024) & 63;
        ((uint32_t*)g_k16)[(((size_t)hd * T_SEQ + row) * 64 + d) >> 1]
            = packh(v1, v0);
    } else {
        int hd = (n - 2048) >> 6, d = (n - 2048) & 63;
        ((uint32_t*)g_v16)[(((size_t)hd * T_SEQ + row) * 64 + d) >> 1]
            = packh(v1, v0);
    }
}

template<int MODE, int TM, int TN, int GSP>
__global__ __launch_bounds__(256, 2)
void gemm_any(const __half* __restrict__ A, const __half* __restrict__ Bt,
              const float* __restrict__ bias, const float* __restrict__ res,
              float* __restrict__ C, int M, int N, int K)
{
    extern __shared__ __align__(1024) char gsm[];
    const int tid = threadIdx.x, wid = tid >> 5, lane = tid & 31;

#if GEMM_TC
    constexpr int A_TILE = TM * 128;
    constexpr int B_TILE = TN * 128;
    constexpr int STAGE  = A_TILE + B_TILE;
    constexpr int TCOLS  = (TM == 256) ? 2 * TN : TN;
    const int m0 = blockIdx.y * TM, n0 = blockIdx.x * TN;
    const uint32_t sb = (uint32_t)__cvta_generic_to_shared(gsm);
    const uint32_t mb0 = sb + 16, mb1 = sb + 24;
    const uint32_t fmb = sb + 32;

    if (wid == 0) {
        asm volatile("tcgen05.alloc.cta_group::1.sync.aligned.shared::cta.b32 [%0], %1;"
                     :: "r"(sb), "r"((uint32_t)TCOLS) : "memory");
        asm volatile("tcgen05.relinquish_alloc_permit.cta_group::1.sync.aligned;");
    }
    if (tid == 0) {
        MBAR_INIT(mb0, 1); MBAR_INIT(mb1, 1);
        MBAR_INIT(fmb + 0, 256); MBAR_INIT(fmb + 8, 256); MBAR_INIT(fmb + 16, 256);
    }
    __syncthreads();
    uint32_t tb;
    asm volatile("ld.shared.b32 %0, [%1];" : "=r"(tb) : "r"(sb));

    const int KT = K >> 6;
    const size_t rowB = (size_t)K * 2;

    auto fill = [&](int slot, int ktile) {
        uint32_t s = sb + G_BASE + slot * STAGE;
        const char* Ab = (const char*)A + ((size_t)m0 * K + (size_t)ktile * 64) * 2;
        const char* Bb = (const char*)Bt + ((size_t)n0 * K + (size_t)ktile * 64) * 2;
        #pragma unroll
        for (int i = 0; i < TM / 32; i++) {
            int idx = tid + i * 256;
            int r = idx >> 3, ch = (idx & 7) * 16;
            uint32_t byte = (uint32_t)(r * 128 + ch);
            uint32_t sw = byte ^ ((byte >> 3) & 0x70);
            cp16(s + sw, Ab + (size_t)r * rowB + ch);
        }
        #pragma unroll
        for (int i = 0; i < TN / 32; i++) {
            int idx = tid + i * 256;
            int r = idx >> 3, ch = (idx & 7) * 16;
            uint32_t byte = (uint32_t)(r * 128 + ch);
            uint32_t sw = byte ^ ((byte >> 3) & 0x70);
            cp16(s + A_TILE + sw, Bb + (size_t)r * rowB + ch);
        }
        CPASYNC_MBAR_ARRIVE_NOINC(fmb + slot * 8);
    };

    #pragma unroll
    for (int st = 0; st < GSP - 1; st++) fill(st, st);

    const uint32_t idesc = (1u << 4) | (0u << 7) | (0u << 10)
                         | ((uint32_t)(TN / 8) << 17) | (8u << 24);

    int ph0 = 0, ph1 = 0;
    for (int kt = 0; kt < KT; kt++) {
        if (wid == 0) {
            int slot = kt % GSP;
            int fph = (kt / GSP) & 1;
            MBAR_WAIT(fmb + slot * 8, fph);
            asm volatile("fence.proxy.async.shared::cta;" ::: "memory");
            if (elect_one()) {
                uint32_t s = sb + G_BASE + slot * STAGE;
                uint64_t ad = make_desc(s);
                uint64_t bd = make_desc(s + A_TILE);
                #pragma unroll
                for (int ks = 0; ks < 4; ks++) {
                    bool acc = (kt > 0) || (ks > 0);
                    tc_mma_f16_ss(tb, ad + ks * 2, bd + ks * 2, idesc, acc);
                    if (TM == 256)
                        tc_mma_f16_ss(tb + TN, ad + 1024 + ks * 2, bd + ks * 2, idesc, acc);
                }
                uint32_t mb = (kt & 1) ? mb1 : mb0;
                asm volatile(
                    "tcgen05.commit.cta_group::1.mbarrier::arrive::one.shared::cluster.b64 [%0];"
                    :: "r"(mb) : "memory");
            }
        }

        if (kt >= 1) {
            if ((kt - 1) & 1) { MBAR_WAIT(mb1, ph1); ph1 ^= 1; }
            else              { MBAR_WAIT(mb0, ph0); ph0 ^= 1; }
        }
        if (kt + GSP - 1 < KT) fill((kt + GSP - 1) % GSP, kt + GSP - 1);
    }

    if ((KT - 1) & 1) { MBAR_WAIT(mb1, ph1); }
    else              { MBAR_WAIT(mb0, ph0); }
    asm volatile("tcgen05.fence::after_thread_sync;" ::: "memory");

    {
        int row; uint32_t dbase; int cstart;
        if (TM == 256) {
            row = m0 + ((wid < 4) ? wid * 32 : 128 + (wid - 4) * 32) + lane;
            dbase = tb + ((wid < 4) ? 0u : (uint32_t)TN);
            cstart = 0;
        } else {
            row = m0 + (wid & 3) * 32 + lane;
            dbase = tb;
            cstart = (wid < 4) ? 0 : TN / 2;
        }
        const int cspan = (TM == 256) ? TN : TN / 2;
        #pragma unroll
        for (int ci = 0; ci < 256; ci += 32) {
            if (ci >= cspan) break;
            const int c0 = cstart + ci;
            float d[32];
            asm volatile(
                "tcgen05.ld.sync.aligned.32x32b.x32.b32 "
                "{%0,%1,%2,%3,%4,%5,%6,%7,%8,%9,%10,%11,%12,%13,%14,%15,"
                "%16,%17,%18,%19,%20,%21,%22,%23,%24,%25,%26,%27,%28,%29,%30,%31}, [%32];"
                : "=f"(d[0]),  "=f"(d[1]),  "=f"(d[2]),  "=f"(d[3]),
                  "=f"(d[4]),  "=f"(d[5]),  "=f"(d[6]),  "=f"(d[7]),
                  "=f"(d[8]),  "=f"(d[9]),  "=f"(d[10]), "=f"(d[11]),
                  "=f"(d[12]), "=f"(d[13]), "=f"(d[14]), "=f"(d[15]),
                  "=f"(d[16]), "=f"(d[17]), "=f"(d[18]), "=f"(d[19]),
                  "=f"(d[20]), "=f"(d[21]), "=f"(d[22]), "=f"(d[23]),
                  "=f"(d[24]), "=f"(d[25]), "=f"(d[26]), "=f"(d[27]),
                  "=f"(d[28]), "=f"(d[29]), "=f"(d[30]), "=f"(d[31])
                : "r"(dbase + c0));
            asm volatile("tcgen05.wait::ld.sync.aligned;" ::: "memory");

            #pragma unroll
            for (int c = 0; c < 32; c += 4) {
                const int n = n0 + c0 + c;
                const float4 bv = *(const float4*)(bias + n);
                float4 v;
                v.x = d[c + 0] + bv.x; v.y = d[c + 1] + bv.y;
                v.z = d[c + 2] + bv.z; v.w = d[c + 3] + bv.w;
                if (MODE == 3) {
                    qkv_write_pair(n,     row, v.x, v.y);
                    qkv_write_pair(n + 2, row, v.z, v.w);
                } else if (MODE == 4) {
                    uint32_t* o16 = (uint32_t*)g_ff16;
                    size_t wi = ((size_t)row * N + n) >> 1;
                    o16[wi]     = packh(gelu_exact(v.y), gelu_exact(v.x));
                    o16[wi + 1] = packh(gelu_exact(v.w), gelu_exact(v.z));
                } else {
                    const float4 rv = *(const float4*)(res + (size_t)row * N + n);
                    v.x += rv.x; v.y += rv.y; v.z += rv.z; v.w += rv.w;
                    *(float4*)(C + (size_t)row * N + n) = v;
                }
            }
        }
    }

    __syncthreads();
    if (tid == 0) {
        asm volatile("mbarrier.inval.shared.b64 [%0];" :: "r"(mb0) : "memory");
        asm volatile("mbarrier.inval.shared.b64 [%0];" :: "r"(mb1) : "memory");
        asm volatile("mbarrier.inval.shared.b64 [%0];" :: "r"(fmb + 0) : "memory");
        asm volatile("mbarrier.inval.shared.b64 [%0];" :: "r"(fmb + 8) : "memory");
        asm volatile("mbarrier.inval.shared.b64 [%0];" :: "r"(fmb + 16) : "memory");
    }
    __syncthreads();
    if (wid == 0)
        asm volatile("tcgen05.dealloc.cta_group::1.sync.aligned.b32 %0, %1;"
                     :: "r"(tb), "r"((uint32_t)TCOLS));

#else
    // ================= mma.sync fp16 fallback: (TM/128)x(TN/128) subtiles =========
    float* As = (float*)gsm;
    float* Bs = As + 2 * 16 * 132;
    #define AS(buf, k, m) As[((buf) * 16 + (k)) * 132 + (m)]
    #define BS(buf, k, n) Bs[((buf) * 16 + (k)) * 132 + (n)]

    const int wm = wid >> 2, wn = wid & 3;
    const int gp = lane >> 2, tg = lane & 3;

    for (int mi = 0; mi < TM / 128; mi++)
    for (int ni = 0; ni < TN / 128; ni++) {
        const int m0 = blockIdx.y * TM + mi * 128;
        const int n0 = blockIdx.x * TN + ni * 128;

        float c[4][4][4];
        #pragma unroll
        for (int i = 0; i < 4; i++)
            #pragma unroll
            for (int j = 0; j < 4; j++)
                #pragma unroll
                for (int r = 0; r < 4; r++) c[i][j][r] = 0.f;

        const int KT = K >> 4;
        float4 va[2], vb[2];

        __syncthreads();
        #pragma unroll
        for (int i = 0; i < 2; i++) {
            int idx = tid + i * 256;
            int r = idx >> 2, c4 = (idx & 3) << 2;
            va[i] = ld4h(A,  (size_t)(m0 + r) * K + c4);
            vb[i] = ld4h(Bt, (size_t)(n0 + r) * K + c4);
        }
        #pragma unroll
        for (int i = 0; i < 2; i++) {
            int idx = tid + i * 256;
            int r = idx >> 2, c4 = (idx & 3) << 2;
            AS(0, c4 + 0, r) = va[i].x; AS(0, c4 + 1, r) = va[i].y;
            AS(0, c4 + 2, r) = va[i].z; AS(0, c4 + 3, r) = va[i].w;
            BS(0, c4 + 0, r) = vb[i].x; BS(0, c4 + 1, r) = vb[i].y;
            BS(0, c4 + 2, r) = vb[i].z; BS(0, c4 + 3, r) = vb[i].w;
        }
        __syncthreads();

        int cur = 0;
        for (int kt = 0; kt < KT; kt++) {
            if (kt + 1 < KT) {
                #pragma unroll
                for (int i = 0; i < 2; i++) {
                    int idx = tid + i * 256;
                    int r = idx >> 2, c4 = (idx & 3) << 2;
                    va[i] = ld4h(A,  (size_t)(m0 + r) * K + (kt + 1) * 16 + c4);
                    vb[i] = ld4h(Bt, (size_t)(n0 + r) * K + (kt + 1) * 16 + c4);
                }
            }
            {
                uint32_t a[4][4], b[4][2];
                #pragma unroll
                for (int mf = 0; mf < 4; mf++) {
                    int r0 = wm * 64 + mf * 16;
                    a[mf][0] = packh(AS(cur, 2*tg+1, r0 + gp    ), AS(cur, 2*tg,   r0 + gp    ));
                    a[mf][1] = packh(AS(cur, 2*tg+1, r0 + gp + 8), AS(cur, 2*tg,   r0 + gp + 8));
                    a[mf][2] = packh(AS(cur, 2*tg+9, r0 + gp    ), AS(cur, 2*tg+8, r0 + gp    ));
                    a[mf][3] = packh(AS(cur, 2*tg+9, r0 + gp + 8), AS(cur, 2*tg+8, r0 + gp + 8));
                }
                #pragma unroll
                for (int nf = 0; nf < 4; nf++) {
                    int c0 = wn * 32 + nf * 8;
                    b[nf][0] = packh(BS(cur, 2*tg+1, c0 + gp), BS(cur, 2*tg,   c0 + gp));
                    b[nf][1] = packh(BS(cur, 2*tg+9, c0 + gp), BS(cur, 2*tg+8, c0 + gp));
                }
                #pragma unroll
                for (int mf = 0; mf < 4; mf++)
                    #pragma unroll
                    for (int nf = 0; nf < 4; nf++)
                        mma_f16(c[mf][nf], a[mf][0], a[mf][1], a[mf][2], a[mf][3],
                                b[nf][0], b[nf][1]);
            }
            if (kt + 1 < KT) {
                int nxt = cur ^ 1;
                #pragma unroll
                for (int i = 0; i < 2; i++) {
                    int idx = tid + i * 256;
                    int r = idx >> 2, c4 = (idx & 3) << 2;
                    AS(nxt, c4 + 0, r) = va[i].x; AS(nxt, c4 + 1, r) = va[i].y;
                    AS(nxt, c4 + 2, r) = va[i].z; AS(nxt, c4 + 3, r) = va[i].w;
                    BS(nxt, c4 + 0, r) = vb[i].x; BS(nxt, c4 + 1, r) = vb[i].y;
                    BS(nxt, c4 + 2, r) = vb[i].z; BS(nxt, c4 + 3, r) = vb[i].w;
                }
                __syncthreads();
                cur = nxt;
            }
        }

        #pragma unroll
        for (int mf = 0; mf < 4; mf++) {
            #pragma unroll
            for (int nf = 0; nf < 4; nf++) {
                int col = n0 + wn * 32 + nf * 8 + 2 * tg;
                float bi0 = bias[col], bi1 = bias[col + 1];
                #pragma unroll
                for (int hh = 0; hh < 2; hh++) {
                    int row = m0 + wm * 64 + mf * 16 + gp + hh * 8;
                    float v0 = c[mf][nf][hh * 2 + 0] + bi0;
                    float v1 = c[mf][nf][hh * 2 + 1] + bi1;
                    if (MODE == 3) {
                        qkv_write_pair(col, row, v0, v1);
                    } else if (MODE == 4) {
                        ((uint32_t*)g_ff16)[((size_t)row * N + col) >> 1]
                            = packh(gelu_exact(v1), gelu_exact(v0));
                    } else {
                        const float2 rv = *(const float2*)(res + (size_t)row * N + col);
                        v0 += rv.x; v1 += rv.y;
                        float2 o; o.x = v0; o.y = v1;
                        *(float2*)(C + (size_t)row * N + col) = o;
                    }
                }
            }
        }
    }
    #undef AS
    #undef BS
#endif
}

// ---------------- causal flash attention (unchanged R15 winner) --------------
#define AQ_OFF  0
#define AK_OFF  4608
#define AV_OFF  9216
#define AM_OFF  13824
#define ATTN_SMEM ((13824 + 128) * 4)   // 55808

__global__ __launch_bounds__(256, 2) void attn_kernel(
    const int* __restrict__ amask, __half* __restrict__ y)
{
    extern __shared__ uint32_t shw[];
    uint32_t* Qs = shw + AQ_OFF;
    uint32_t* Ks = shw + AK_OFF;
    uint32_t* Vs = shw + AV_OFF;
    int*      mk = (int*)(shw + AM_OFF);

    const int tid = threadIdx.x, lane = tid & 31, w = tid >> 5;
    const int gp = lane >> 2, tg = lane & 3;
    const int h = blockIdx.y;
    const int q0 = (gridDim.x - 1 - blockIdx.x) * 128;
    const int qw = q0 + w * 16;

    const int lm = lane >> 3, lr = lane & 7;
    const uint32_t koff = (uint32_t)(((lm >> 1) * 8 + lr) * 144 + (lm & 1) * 16);
    const uint32_t voff = (uint32_t)(((lm & 1) * 8 + lr) * 144 + (lm >> 1) * 16);
    const uint32_t Kb = (uint32_t)__cvta_generic_to_shared(Ks);
    const uint32_t Vb = (uint32_t)__cvta_generic_to_shared(Vs);

    {
        const __half* qb = g_q16 + ((size_t)h * T_SEQ + q0) * 64;
        #pragma unroll
        for (int i = 0; i < 4; i++) {
            int idx = tid + i * 256;
            int r = idx >> 3, ch = idx & 7;
            cp16((uint32_t)__cvta_generic_to_shared(Qs + r * 36 + ch * 4),
                 qb + (size_t)r * 64 + ch * 8);
        }
    }
    asm volatile("cp.async.commit_group;" ::: "memory");

    if (tid < 128) {
        int buf = tid >> 6, r = tid & 63;
        uint32_t* vr = Vs + buf * 2304 + r * 36;
        vr[32] = 0x00003C00u; vr[33] = 0u; vr[34] = 0u; vr[35] = 0u;
    }

    auto fill_kv = [&](int buf, int kt) {
        const __half* kbs = g_k16 + ((size_t)h * T_SEQ + kt * 64) * 64;
        const __half* vbs = g_v16 + ((size_t)h * T_SEQ + kt * 64) * 64;
        #pragma unroll
        for (int i = 0; i < 2; i++) {
            int idx = tid + i * 256;
            int r = idx >> 3, ch = idx & 7;
            cp16((uint32_t)__cvta_generic_to_shared(Ks + buf * 2304 + r * 36 + ch * 4),
                 kbs + (size_t)r * 64 + ch * 8);
            cp16((uint32_t)__cvta_generic_to_shared(Vs + buf * 2304 + r * 36 + ch * 4),
                 vbs + (size_t)r * 64 + ch * 8);
        }
        if (tid < 16)
            cp16((uint32_t)__cvta_generic_to_shared(mk + buf * 64 + tid * 4),
                 amask + kt * 64 + tid * 4);
    };

    fill_kv(0, 0);
    asm volatile("cp.async.commit_group;" ::: "memory");
    asm volatile("cp.async.wait_group 0;" ::: "memory");
    __syncthreads();

    uint32_t qa[4][4];
    {
        int r0 = w * 16;
        #pragma unroll
        for (int ks = 0; ks < 4; ks++) {
            qa[ks][0] = Qs[(r0 + gp    ) * 36 + 8 * ks + tg    ];
            qa[ks][1] = Qs[(r0 + gp + 8) * 36 + 8 * ks + tg    ];
            qa[ks][2] = Qs[(r0 + gp    ) * 36 + 8 * ks + 4 + tg];
            qa[ks][3] = Qs[(r0 + gp + 8) * 36 + 8 * ks + 4 + tg];
        }
    }

    float m0 = -INFINITY, m1 = -INFINITY;
    float o[9][4];
    #pragma unroll
    for (int nf = 0; nf < 9; nf++)
        #pragma unroll
        for (int r = 0; r < 4; r++) o[nf][r] = 0.f;

    const uint32_t onesb = (gp == 0) ? 0x3C003C00u : 0u;

    const int ktmax = (q0 + 127) >> 6;
    const int kdiag = q0 >> 6;
    const int row0 = qw + gp, row1 = qw + gp + 8;
    int cur = 0;

    for (int kt = 0; kt <= ktmax; kt++) {
        asm volatile("cp.async.wait_group 0;" ::: "memory");
        __syncthreads();

        if (kt < ktmax) {
            fill_kv(cur ^ 1, kt + 1);
            asm volatile("cp.async.commit_group;" ::: "memory");
        }

        const uint32_t Kcur = Kb + cur * 9216;
        const uint32_t Vcur = Vb + cur * 9216;
        const int*     M    = mk + cur * 64;
        const bool diag = (kt >= kdiag);

        float sc[8][4];
        #pragma unroll
        for (int nf = 0; nf < 8; nf++)
            #pragma unroll
            for (int r = 0; r < 4; r++) sc[nf][r] = 0.f;

        #pragma unroll
        for (int ks = 0; ks < 4; ks++) {
            #pragma unroll
            for (int j = 0; j < 4; j++) {
                uint32_t kb[4];
                ldsm4(kb, Kcur + j * 2304 + ks * 32 + koff);
                mma_f16(sc[2*j],   qa[ks][0], qa[ks][1], qa[ks][2], qa[ks][3], kb[0], kb[1]);
                mma_f16(sc[2*j+1], qa[ks][0], qa[ks][1], qa[ks][2], qa[ks][3], kb[2], kb[3]);
            }
        }

        float tm0 = -INFINITY, tm1 = -INFINITY;
        if (diag) {
            #pragma unroll
            for (int nf = 0; nf < 8; nf++) {
                int cl = nf * 8 + 2 * tg;
                int c  = kt * 64 + cl;
                bool mk0 = M[cl] != 0, mk1 = M[cl + 1] != 0;
                float s0 = sc[nf][0], s1 = sc[nf][1];
                float s2 = sc[nf][2], s3 = sc[nf][3];
                s0 = (c     <= row0 && mk0) ? s0 : -INFINITY;
                s1 = (c + 1 <= row0 && mk1) ? s1 : -INFINITY;
                s2 = (c     <= row1 && mk0) ? s2 : -INFINITY;
                s3 = (c + 1 <= row1 && mk1) ? s3 : -INFINITY;
                sc[nf][0] = s0; sc[nf][1] = s1; sc[nf][2] = s2; sc[nf][3] = s3;
                tm0 = fmaxf(tm0, fmaxf(s0, s1));
                tm1 = fmaxf(tm1, fmaxf(s2, s3));
            }
        } else {
            #pragma unroll
            for (int nf = 0; nf < 8; nf++) {
                int cl = nf * 8 + 2 * tg;
                bool mk0 = M[cl] != 0, mk1 = M[cl + 1] != 0;
                float s0 = mk0 ? sc[nf][0] : -INFINITY;
                float s1 = mk1 ? sc[nf][1] : -INFINITY;
                float s2 = mk0 ? sc[nf][2] : -INFINITY;
                float s3 = mk1 ? sc[nf][3] : -INFINITY;
                sc[nf][0] = s0; sc[nf][1] = s1; sc[nf][2] = s2; sc[nf][3] = s3;
                tm0 = fmaxf(tm0, fmaxf(s0, s1));
                tm1 = fmaxf(tm1, fmaxf(s2, s3));
            }
        }
        tm0 = fmaxf(tm0, __shfl_xor_sync(0xffffffffu, tm0, 1));
        tm0 = fmaxf(tm0, __shfl_xor_sync(0xffffffffu, tm0, 2));
        tm1 = fmaxf(tm1, __shfl_xor_sync(0xffffffffu, tm1, 1));
        tm1 = fmaxf(tm1, __shfl_xor_sync(0xffffffffu, tm1, 2));

        float nm0 = fmaxf(m0, tm0), nm1 = fmaxf(m1, tm1);
        float ne0 = fmaxf(nm0, -1e30f), ne1 = fmaxf(nm1, -1e30f);
        float al0 = ex2(m0 - ne0), al1 = ex2(m1 - ne1);
        m0 = nm0; m1 = nm1;

        #pragma unroll
        for (int nf = 0; nf < 9; nf++) {
            o[nf][0] *= al0; o[nf][1] *= al0;
            o[nf][2] *= al1; o[nf][3] *= al1;
        }

        #pragma unroll
        for (int ks = 0; ks < 4; ks++) {
            uint32_t pa0 = ex2h2(packh(sc[2*ks  ][1] - ne0, sc[2*ks  ][0] - ne0));
            uint32_t pa1 = ex2h2(packh(sc[2*ks  ][3] - ne1, sc[2*ks  ][2] - ne1));
            uint32_t pa2 = ex2h2(packh(sc[2*ks+1][1] - ne0, sc[2*ks+1][0] - ne0));
            uint32_t pa3 = ex2h2(packh(sc[2*ks+1][3] - ne1, sc[2*ks+1][2] - ne1));
            #pragma unroll
            for (int j = 0; j < 4; j++) {
                uint32_t vb[4];
                ldsm4t(vb, Vcur + ks * 2304 + j * 32 + voff);
                mma_f16(o[2*j],   pa0, pa1, pa2, pa3, vb[0], vb[1]);
                mma_f16(o[2*j+1], pa0, pa1, pa2, pa3, vb[2], vb[3]);
            }
            mma_f16(o[8], pa0, pa1, pa2, pa3, onesb, onesb);
        }
        cur ^= 1;
    }

    float l0 = __shfl_sync(0xffffffffu, o[8][0], lane & ~3);
    float l1 = __shfl_sync(0xffffffffu, o[8][2], lane & ~3);
    float il0 = 1.0f / fmaxf(l0, 1e-30f);
    float il1 = 1.0f / fmaxf(l1, 1e-30f);
    uint32_t* yw = (uint32_t*)y;
    #pragma unroll
    for (int nf = 0; nf < 8; nf++) {
        int col = h * HDIM + nf * 8 + 2 * tg;
        yw[((size_t)row0 * DM + col) >> 1] = packh(o[nf][1] * il0, o[nf][0] * il0);
        yw[((size_t)row1 * DM + col) >> 1] = packh(o[nf][3] * il1, o[nf][2] * il1);
    }
}

// ---------------- launcher ----------------
extern "C" void kernel_launch(void* const* d_in, const int* in_sizes, int n_in,
                              void* d_out, int out_size)
{
    const float* x     = (const float*)d_in[0];
    const int*   amask = (const int*)  d_in[1];
    const float* ln1g  = (const float*)d_in[2];
    const float* ln1b  = (const float*)d_in[3];
    const float* Wqkv  = (const float*)d_in[4];
    const float* bqkv  = (const float*)d_in[5];
    const float* Wo    = (const float*)d_in[6];
    const float* bo    = (const float*)d_in[7];
    const float* ln2g  = (const float*)d_in[8];
    const float* ln2b  = (const float*)d_in[9];
    const float* W1    = (const float*)d_in[10];
    const float* b1    = (const float*)d_in[11];
    const float* W2    = (const float*)d_in[12];
    const float* b2    = (const float*)d_in[13];
    float* out = (float*)d_out;

    void *p_x2, *p_wqkv, *p_wo, *p_w1, *p_w2, *p_ln16, *p_y16, *p_ff16;
    cudaGetSymbolAddress(&p_x2,   g_x2);
    cudaGetSymbolAddress(&p_wqkv, g_wqkv16);
    cudaGetSymbolAddress(&p_wo,   g_wo16);
    cudaGetSymbolAddress(&p_w1,   g_w1_16);
    cudaGetSymbolAddress(&p_w2,   g_w2_16);
    cudaGetSymbolAddress(&p_ln16, g_ln16);
    cudaGetSymbolAddress(&p_y16,  g_y16);
    cudaGetSymbolAddress(&p_ff16, g_ff16);

    const int GSM = G_SMEM_T(128, 256, 2);   // 99328 -> 2 CTAs/SM

    cudaFuncSetAttribute(attn_kernel,
        cudaFuncAttributeMaxDynamicSharedMemorySize, ATTN_SMEM);
    cudaFuncSetAttribute(gemm_any<3, 128, 256, 2>,
        cudaFuncAttributeMaxDynamicSharedMemorySize, GSM);
    cudaFuncSetAttribute(gemm_any<4, 128, 256, 2>,
        cudaFuncAttributeMaxDynamicSharedMemorySize, GSM);
    cudaFuncSetAttribute(gemm_any<5, 128, 256, 2>,
        cudaFuncAttributeMaxDynamicSharedMemorySize, GSM);

    // 0-1. weight transposes (two launches; keeps QKV at capture idx 3)
    transpose_qo <<<4096, 256>>>(Wqkv, Wo, (__half*)p_wqkv, (__half*)p_wo);
    transpose_w12<<<8192, 256>>>(W1, W2, (__half*)p_w1, (__half*)p_w2);

    // 2. LN1 -> fp16
    ln_kernel<<<T_SEQ, 256>>>(x, ln1g, ln1b, (__half*)p_ln16);
    // 3. QKV -> fp16 q/k/v buffers   (384 CTAs, 2/SM)
    gemm_any<3, 128, 256, 2><<<dim3(12, 32), 256, GSM>>>(
        (__half*)p_ln16, (__half*)p_wqkv, bqkv, nullptr, nullptr, T_SEQ, 3 * DM, DM);
    // 4. attention -> fp16 y
    attn_kernel<<<dim3(32, 16), 256, ATTN_SMEM>>>(amask, (__half*)p_y16);
    // 5. x2 = x + y @ W_o + b_o   (128 CTAs, 2/SM)
    gemm_any<5, 128, 256, 2><<<dim3(4, 32), 256, GSM>>>(
        (__half*)p_y16, (__half*)p_wo, bo, x, (float*)p_x2, T_SEQ, DM, DM);
    // 6. LN2 -> fp16
    ln_kernel<<<T_SEQ, 256>>>((float*)p_x2, ln2g, ln2b, (__half*)p_ln16);
    // 7. FF1: gelu -> fp16 g_ff16   (512 CTAs, 2/SM)
    gemm_any<4, 128, 256, 2><<<dim3(16, 32), 256, GSM>>>(
        (__half*)p_ln16, (__half*)p_w1, b1, nullptr, nullptr, T_SEQ, DFF, DM);
    // 8. FF2: out = x2 + ff @ W2 + b2   (128 CTAs, 2/SM)
    gemm_any<5, 128, 256, 2><<<dim3(4, 32), 256, GSM>>>(
        (__half*)p_ff16, (__half*)p_w2, b2, (float*)p_x2, out, T_SEQ, DM, DFF);
}